// round 2
// baseline (speedup 1.0000x reference)
#include <cuda_runtime.h>
#include <cstdint>

#define BB 64
#define CC 512
#define HWHW 1024
#define NN 4
#define DD 128
#define KK 1024
// P = BB*HWHW = 65536

// -------- scratch (no allocs allowed) --------
__device__ float d_eNorm[NN * KK];                 // ||e||^2 per (n,k)
__device__ float d_embedT[(size_t)NN * KK * DD];   // embed transposed [n][k][d]
__device__ int   d_idxBuf[BB * NN * HWHW];         // argmin per (b,n,hw)
__device__ int   d_counts[NN * KK];
__device__ float d_diffPartial[32 * 64 * 4];       // 8192 partials

// packed fp32x2 helpers (sm_103a FFMA2 path — PTX-only, IEEE-exact per lane)
__device__ __forceinline__ unsigned long long pk2(float lo, float hi) {
    unsigned long long r;
    asm("mov.b64 %0, {%1, %2};" : "=l"(r) : "f"(lo), "f"(hi));
    return r;
}
__device__ __forceinline__ void fma2(unsigned long long& d,
                                     unsigned long long a,
                                     unsigned long long b) {
    asm("fma.rn.f32x2 %0, %1, %2, %0;" : "+l"(d) : "l"(a), "l"(b));
}
__device__ __forceinline__ void unpk2(unsigned long long v, float& lo, float& hi) {
    asm("mov.b64 {%0, %1}, %2;" : "=f"(lo), "=f"(hi) : "l"(v));
}

// ============================================================
// Kernel A: eNorm + transposed codebook + zero counts
// ============================================================
__global__ void prep_kernel(const float* __restrict__ embed) {
    const int n  = blockIdx.x >> 3;
    const int kc = blockIdx.x & 7;
    const int k  = kc * 128 + threadIdx.x;
    const float* e = embed + (size_t)n * DD * KK + k;
    float* tB = d_embedT + ((size_t)(n * KK + k)) * DD;
    float s = 0.f;
#pragma unroll 8
    for (int d = 0; d < DD; d++) {
        float v = e[(size_t)d * KK];
        s = fmaf(v, v, s);
        tB[d] = v;
    }
    d_eNorm[n * KK + k] = s;
    d_counts[blockIdx.x * 128 + threadIdx.x] = 0;
}

// ============================================================
// Kernel B: fused distance GEMM + running argmin (FFMA2 inner loop)
// grid (8 hwTiles, 64 b, 4 n), 256 threads, 128x128 tile, D=128
// dist = ||e||^2 - 2*z.e  (||z||^2 constant per point, dropped)
// ============================================================
__global__ __launch_bounds__(256, 1)
void vq_main(const float* __restrict__ x,
             const float* __restrict__ embed,
             float* __restrict__ argmin_out) {
    extern __shared__ float sm[];
    float* zs  = sm;            // [128 d][128 pt]
    float* es  = sm + 16384;    // [128 d][128 k]
    float* eNs = sm + 32768;    // [128]

    const int tid = threadIdx.x;
    const int tx = tid & 15;        // code dir (8 codes)
    const int ty = tid >> 4;        // point dir (8 points)
    const int hw0 = blockIdx.x * 128;
    const int b = blockIdx.y;
    const int n = blockIdx.z;

    // ---- load Z tile: zs[d][pt] = x[b][n*128+d][hw0+pt]
    const float* xblk = x + ((size_t)b * CC + n * DD) * HWHW + hw0;
#pragma unroll
    for (int r = 0; r < 16; r++) {
        int l = r * 256 + tid;
        int d = l >> 5, q = l & 31;     // 32 float4 per 128-float row
        ((float4*)zs)[d * 32 + q] = __ldg((const float4*)(xblk + (size_t)d * HWHW) + q);
    }

    float best[8];
    int   bk[8];
#pragma unroll
    for (int i = 0; i < 8; i++) { best[i] = 3.4e38f; bk[i] = 0; }

    const float* eblk = embed + (size_t)n * DD * KK;

    for (int kc = 0; kc < 8; kc++) {
        __syncthreads();   // guard es reuse (and zs store on first iter)
#pragma unroll
        for (int r = 0; r < 16; r++) {
            int l = r * 256 + tid;
            int d = l >> 5, q = l & 31;
            ((float4*)es)[d * 32 + q] =
                __ldg((const float4*)(eblk + (size_t)d * KK + kc * 128) + q);
        }
        if (tid < 32)
            ((float4*)eNs)[tid] = *((const float4*)(d_eNorm + n * KK + kc * 128) + tid);
        __syncthreads();

        // accumulators packed along the POINT axis: acc2[i2][j] = {pt 2*i2, pt 2*i2+1}
        unsigned long long acc2[4][8];
#pragma unroll
        for (int i2 = 0; i2 < 4; i2++)
#pragma unroll
            for (int j = 0; j < 8; j++) acc2[i2][j] = pk2(0.f, 0.f);

#pragma unroll 8
        for (int d = 0; d < 128; d++) {
            // point pairs come free: adjacent floats in zs
            const ulonglong2 zA = *(const ulonglong2*)(zs + d * 128 + ty * 8);
            const ulonglong2 zB = *(const ulonglong2*)(zs + d * 128 + ty * 8 + 4);
            const unsigned long long zp[4] = {zA.x, zA.y, zB.x, zB.y};
            // e broadcast packs {e,e}
            const float4 e0 = *(const float4*)(es + d * 128 + tx * 8);
            const float4 e1 = *(const float4*)(es + d * 128 + tx * 8 + 4);
            unsigned long long ep[8];
            ep[0] = pk2(e0.x, e0.x); ep[1] = pk2(e0.y, e0.y);
            ep[2] = pk2(e0.z, e0.z); ep[3] = pk2(e0.w, e0.w);
            ep[4] = pk2(e1.x, e1.x); ep[5] = pk2(e1.y, e1.y);
            ep[6] = pk2(e1.z, e1.z); ep[7] = pk2(e1.w, e1.w);
#pragma unroll
            for (int j = 0; j < 8; j++)
#pragma unroll
                for (int i2 = 0; i2 < 4; i2++)
                    fma2(acc2[i2][j], zp[i2], ep[j]);
        }

        // fold this chunk into the running argmin
#pragma unroll
        for (int j = 0; j < 8; j++) {
            const float en = eNs[tx * 8 + j];
            const int kk = kc * 128 + tx * 8 + j;
#pragma unroll
            for (int i2 = 0; i2 < 4; i2++) {
                float alo, ahi;
                unpk2(acc2[i2][j], alo, ahi);
                float vlo = fmaf(-2.f, alo, en);
                float vhi = fmaf(-2.f, ahi, en);
                if (vlo < best[2 * i2])     { best[2 * i2] = vlo;     bk[2 * i2] = kk; }
                if (vhi < best[2 * i2 + 1]) { best[2 * i2 + 1] = vhi; bk[2 * i2 + 1] = kk; }
            }
        }
    }

    // ---- merge across the 16 tx lanes (jnp tie-break: smallest k)
#pragma unroll
    for (int i = 0; i < 8; i++) {
        float v = best[i];
        int kk = bk[i];
#pragma unroll
        for (int off = 8; off; off >>= 1) {
            float ov = __shfl_xor_sync(0xFFFFFFFFu, v, off);
            int   ok = __shfl_xor_sync(0xFFFFFFFFu, kk, off);
            if (ov < v || (ov == v && ok < kk)) { v = ov; kk = ok; }
        }
        if (tx == 0) {
            const int hw = hw0 + ty * 8 + i;
            const int o = (b * NN + n) * HWHW + hw;
            d_idxBuf[o] = kk;
            argmin_out[o] = (float)kk;
            atomicAdd(&d_counts[n * KK + kk], 1);
        }
    }
}

// ============================================================
// Kernel C: gather q, write z_q = z + (q - z), diff partials
// grid (32 hwTiles of 32 pts, 64 b, 4 n), 256 threads
// ============================================================
__global__ __launch_bounds__(256)
void epi_kernel(const float* __restrict__ x, float* __restrict__ zq) {
    __shared__ float qs[128 * 33];   // [d][pt], padded
    __shared__ float red[256];

    const int tid = threadIdx.x;
    const int hw0 = blockIdx.x * 32;
    const int b = blockIdx.y;
    const int n = blockIdx.z;
    const int lane = tid & 31;
    const int w = tid >> 5;

#pragma unroll
    for (int pp = 0; pp < 4; pp++) {
        const int pt = w * 4 + pp;
        const int k = d_idxBuf[(b * NN + n) * HWHW + hw0 + pt];
        const float4 v = *((const float4*)(d_embedT + ((size_t)(n * KK + k)) * DD) + lane);
        const int d = lane * 4;
        qs[(d + 0) * 33 + pt] = v.x;
        qs[(d + 1) * 33 + pt] = v.y;
        qs[(d + 2) * 33 + pt] = v.z;
        qs[(d + 3) * 33 + pt] = v.w;
    }
    __syncthreads();

    float lsum = 0.f;
    const int hw = tid & 31;
    const int dh = tid >> 5;   // 0..7
#pragma unroll
    for (int d0 = 0; d0 < 128; d0 += 8) {
        const int d = d0 + dh;
        const size_t off = ((size_t)b * CC + n * DD + d) * HWHW + hw0 + hw;
        const float xv = __ldg(x + off);
        const float q = qs[d * 33 + hw];
        const float t = q - xv;
        zq[off] = xv + t;           // matches z + stopgrad(q - z) in fp32
        lsum = fmaf(t, t, lsum);
    }

    red[tid] = lsum;
    __syncthreads();
    for (int s = 128; s; s >>= 1) {
        if (tid < s) red[tid] += red[tid + s];
        __syncthreads();
    }
    if (tid == 0)
        d_diffPartial[(blockIdx.z * 64 + blockIdx.y) * 32 + blockIdx.x] = red[0];
}

// ============================================================
// Kernel D: final diff + ppl (single block, deterministic trees)
// ============================================================
__global__ void final_kernel(float* __restrict__ out_diff, float* __restrict__ out_ppl) {
    __shared__ float red[1024];
    __shared__ float ent[NN];
    const int tid = threadIdx.x;

    float s = 0.f;
#pragma unroll
    for (int r = 0; r < 8; r++) s += d_diffPartial[r * 1024 + tid];
    red[tid] = s;
    __syncthreads();
    for (int st = 512; st; st >>= 1) {
        if (tid < st) red[tid] += red[tid + st];
        __syncthreads();
    }
    if (tid == 0) *out_diff = red[0] / 33554432.0f;
    __syncthreads();

    for (int n = 0; n < NN; n++) {
        const float c = (float)d_counts[n * KK + tid];
        const float p = c * (1.0f / 65536.0f);
        red[tid] = p * logf(p + 1e-10f);
        __syncthreads();
        for (int st = 512; st; st >>= 1) {
            if (tid < st) red[tid] += red[tid + st];
            __syncthreads();
        }
        if (tid == 0) ent[n] = red[0];
        __syncthreads();
    }
    if (tid == 0) {
        float ppl = 0.f;
        for (int n = 0; n < NN; n++) ppl += expf(-ent[n]);
        *out_ppl = ppl * 0.25f;
    }
}

// ============================================================
extern "C" void kernel_launch(void* const* d_in, const int* in_sizes, int n_in,
                              void* d_out, int out_size) {
    const float* x     = (const float*)d_in[0];
    const float* embed = (const float*)d_in[1];
    if (in_sizes[0] == NN * DD * KK) {  // defensive: inputs swapped
        x     = (const float*)d_in[1];
        embed = (const float*)d_in[0];
    }

    float* out = (float*)d_out;
    float* zq    = out;                          // 33554432
    float* diff  = out + 33554432;               // 1
    float* argm  = out + 33554433;               // 262144
    float* ppl   = out + 33554433 + 262144;      // 1

    const int smem_main = (16384 + 16384 + 128) * (int)sizeof(float);  // 131584 B
    cudaFuncSetAttribute(vq_main, cudaFuncAttributeMaxDynamicSharedMemorySize, smem_main);

    prep_kernel<<<32, 128>>>(embed);
    vq_main<<<dim3(8, 64, 4), 256, smem_main>>>(x, embed, argm);
    epi_kernel<<<dim3(32, 64, 4), 256>>>(x, zq);
    final_kernel<<<1, 1024>>>(diff, ppl);
}

// round 6
// speedup vs baseline: 1.1746x; 1.1746x over previous
#include <cuda_runtime.h>
#include <cstdint>

#define BB 64
#define CC 512
#define HWHW 1024
#define NN 4
#define DD 128
#define KK 1024
// P = 65536 points

// -------- scratch --------
__device__ __align__(16) float d_eNorm[NN * KK];
__device__ __align__(16) float d_embedT[(size_t)NN * KK * DD];   // fp32 [n][k][d] for epi gather
__device__ int   d_idxBuf[BB * NN * HWHW];
__device__ int   d_counts[NN * KK];
__device__ __align__(16) float d_diffPartial[8192];

__device__ __forceinline__ uint32_t f2tf32(float f) {
    uint32_t u;
    asm("cvt.rna.tf32.f32 %0, %1;" : "=r"(u) : "f"(f));
    return u;
}

// legacy warp-level tensor mma (sm_80+, plain target — no 'a' features)
__device__ __forceinline__ void mma8(float* c, const uint32_t* a, uint32_t b0, uint32_t b1) {
    asm volatile(
        "mma.sync.aligned.m16n8k8.row.col.f32.tf32.tf32.f32 "
        "{%0,%1,%2,%3}, {%4,%5,%6,%7}, {%8,%9}, {%0,%1,%2,%3};"
        : "+f"(c[0]), "+f"(c[1]), "+f"(c[2]), "+f"(c[3])
        : "r"(a[0]), "r"(a[1]), "r"(a[2]), "r"(a[3]), "r"(b0), "r"(b1));
}

// ============================================================
// Kernel A: eNorm + transposed codebook + zero counts
// ============================================================
__global__ void prep_kernel(const float* __restrict__ embed) {
    const int n  = blockIdx.x >> 3;
    const int kc = blockIdx.x & 7;
    const int k  = kc * 128 + threadIdx.x;
    const float* e = embed + (size_t)n * DD * KK + k;
    float* tB = d_embedT + ((size_t)(n * KK + k)) * DD;
    float s = 0.f;
#pragma unroll 8
    for (int d = 0; d < DD; d++) {
        float v = e[(size_t)d * KK];
        s = fmaf(v, v, s);
        tB[d] = v;
    }
    d_eNorm[n * KK + k] = s;
    d_counts[blockIdx.x * 128 + threadIdx.x] = 0;
}

// ============================================================
// Kernel B: tf32 3-split mma.sync distance GEMM + fused argmin
// grid (512, 4): 128 pt x 1024 codes/block, 256 thr (8 warps)
// warp grid 4(pt) x 2(cd); warp tile 32pt x 64cd; K=128 in 16 k8-steps
// smem [k][m] stride 136 -> conflict-free fragment loads (8t+g banks)
// ============================================================
#define ZSTR 136
#define SM_ES   17408          // words
#define SM_ENS  34816
#define SM_WORDS 34944         // 139,776 bytes

__global__ __launch_bounds__(256, 1)
void vq_mma(const float* __restrict__ x, const float* __restrict__ embed,
            float* __restrict__ argmin_out) {
    extern __shared__ float sm[];
    float* zs  = sm;                 // [128 k][128 pt] stride 136
    float* es  = sm + SM_ES;         // [128 k][128 cd] stride 136
    float* eNs = sm + SM_ENS;        // [128]

    const int tid = threadIdx.x;
    const int wid = tid >> 5;
    const int lane = tid & 31;
    const int g = lane >> 2;         // 0..7
    const int t = lane & 3;          // 0..3
    const int b = blockIdx.x >> 3;
    const int hw0 = (blockIdx.x & 7) * 128;
    const int n = blockIdx.y;
    const int ptb = (wid >> 1) * 32;     // warp point base (block-local)
    const int cdw = (wid & 1) * 64;      // warp code base within chunk

    // ---- stage z tile once: zs[d][pt] = x[b][n*128+d][hw0+pt]
    const float* xblk = x + ((size_t)b * CC + n * DD) * HWHW + hw0;
#pragma unroll
    for (int r = 0; r < 16; r++) {
        int l = r * 256 + tid;
        int d = l >> 5, q = l & 31;
        *(float4*)(zs + d * ZSTR + q * 4) = __ldg((const float4*)(xblk + (size_t)d * HWHW) + q);
    }

    float best[4] = {3.4e38f, 3.4e38f, 3.4e38f, 3.4e38f};
    int   bk[4]   = {0, 0, 0, 0};

    const float* eblk = embed + (size_t)n * DD * KK;

    for (int c = 0; c < 8; c++) {
        // ---- stage e chunk: es[d][cd] = embed[n][d][c*128+cd]
        const float* ebl = eblk + c * 128;
#pragma unroll
        for (int r = 0; r < 16; r++) {
            int l = r * 256 + tid;
            int d = l >> 5, q = l & 31;
            *(float4*)(es + d * ZSTR + q * 4) = __ldg((const float4*)(ebl + (size_t)d * KK) + q);
        }
        if (tid < 32)
            ((float4*)eNs)[tid] = __ldg((const float4*)(d_eNorm + n * KK + c * 128) + tid);
        __syncthreads();

        float acc[2][8][4];
#pragma unroll
        for (int mf = 0; mf < 2; mf++)
#pragma unroll
            for (int nf = 0; nf < 8; nf++)
#pragma unroll
                for (int i = 0; i < 4; i++) acc[mf][nf][i] = 0.f;

#pragma unroll 4
        for (int ks = 0; ks < 16; ks++) {
            const float* zr = zs + (ks * 8 + t) * ZSTR + ptb + g;
            // A fragments (rows=pt, cols=k): a0..a3 = (g,t),(g+8,t),(g,t+4),(g+8,t+4)
            float zv[2][4];
            zv[0][0] = zr[0];        zv[0][1] = zr[8];
            zv[0][2] = zr[4 * ZSTR]; zv[0][3] = zr[4 * ZSTR + 8];
            zv[1][0] = zr[16];       zv[1][1] = zr[24];
            zv[1][2] = zr[4 * ZSTR + 16]; zv[1][3] = zr[4 * ZSTR + 24];
            uint32_t ah[2][4], al[2][4];
#pragma unroll
            for (int mf = 0; mf < 2; mf++)
#pragma unroll
                for (int i = 0; i < 4; i++) {
                    uint32_t h = f2tf32(zv[mf][i]);
                    ah[mf][i] = h;
                    al[mf][i] = f2tf32(zv[mf][i] - __uint_as_float(h));
                }

            const float* er = es + (ks * 8 + t) * ZSTR + cdw + g;
#pragma unroll
            for (int nf = 0; nf < 8; nf++) {
                // B fragment (k8 x n8, col): b0=(t, g), b1=(t+4, g)
                float fb0 = er[nf * 8];
                float fb1 = er[nf * 8 + 4 * ZSTR];
                uint32_t bh0 = f2tf32(fb0);
                uint32_t bl0 = f2tf32(fb0 - __uint_as_float(bh0));
                uint32_t bh1 = f2tf32(fb1);
                uint32_t bl1 = f2tf32(fb1 - __uint_as_float(bh1));
                mma8(acc[0][nf], ah[0], bh0, bh1);   // hi*hi
                mma8(acc[0][nf], al[0], bh0, bh1);   // lo*hi
                mma8(acc[0][nf], ah[0], bl0, bl1);   // hi*lo
                mma8(acc[1][nf], ah[1], bh0, bh1);
                mma8(acc[1][nf], al[1], bh0, bh1);
                mma8(acc[1][nf], ah[1], bl0, bl1);
            }
        }

        // ---- fold chunk into running argmin
        // C frag: c0=(g,2t) c1=(g,2t+1) c2=(g+8,2t) c3=(g+8,2t+1)
#pragma unroll
        for (int nf = 0; nf < 8; nf++) {
            const float e0 = eNs[cdw + nf * 8 + 2 * t];
            const float e1 = eNs[cdw + nf * 8 + 2 * t + 1];
            const int kg = c * 128 + cdw + nf * 8 + 2 * t;
#pragma unroll
            for (int mf = 0; mf < 2; mf++) {
                float d0 = fmaf(-2.f, acc[mf][nf][0], e0);
                float d1 = fmaf(-2.f, acc[mf][nf][1], e1);
                float d2 = fmaf(-2.f, acc[mf][nf][2], e0);
                float d3 = fmaf(-2.f, acc[mf][nf][3], e1);
                const int s0 = mf * 2, s1 = mf * 2 + 1;   // rows g(+16), g+8(+16)
                if (d0 < best[s0]) { best[s0] = d0; bk[s0] = kg; }
                if (d1 < best[s0]) { best[s0] = d1; bk[s0] = kg + 1; }
                if (d2 < best[s1]) { best[s1] = d2; bk[s1] = kg; }
                if (d3 < best[s1]) { best[s1] = d3; bk[s1] = kg + 1; }
            }
        }
        __syncthreads();   // es reuse next chunk / smem reuse for merge
    }

    // ---- merge across the 4 t-lanes of each quad (tie: smallest k)
#pragma unroll
    for (int s = 0; s < 4; s++) {
        float v = best[s]; int kk = bk[s];
#pragma unroll
        for (int off = 1; off <= 2; off <<= 1) {
            float ov = __shfl_xor_sync(0xFFFFFFFFu, v, off);
            int   ok = __shfl_xor_sync(0xFFFFFFFFu, kk, off);
            if (ov < v || (ov == v && ok < kk)) { v = ov; kk = ok; }
        }
        best[s] = v; bk[s] = kk;
    }

    // ---- merge warp pairs (cd halves) via smem, then write
    float* mb = zs;                 // rows 0..127
    int*   mk = (int*)es;
    const int rowoff[4] = {g, 8 + g, 16 + g, 24 + g};
    if ((wid & 1) == 0 && t == 0) {
#pragma unroll
        for (int s = 0; s < 4; s++) { mb[ptb + rowoff[s]] = best[s]; mk[ptb + rowoff[s]] = bk[s]; }
    }
    __syncthreads();
    if ((wid & 1) == 1 && t == 0) {
#pragma unroll
        for (int s = 0; s < 4; s++) {
            const int row = ptb + rowoff[s];
            float ov = mb[row]; int ok = mk[row];
            float v = best[s]; int kk = bk[s];
            if (ov < v || (ov == v && ok < kk)) { v = ov; kk = ok; }
            const int o = (b * NN + n) * HWHW + hw0 + row;
            d_idxBuf[o] = kk;
            argmin_out[o] = (float)kk;
            atomicAdd(&d_counts[n * KK + kk], 1);
        }
    }
}

// ============================================================
// Kernel C: gather q, z_q, diff partials
// ============================================================
__global__ __launch_bounds__(256)
void epi_kernel(const float* __restrict__ x, float* __restrict__ zq) {
    __shared__ float qs[128 * 33];
    __shared__ float red[256];
    const int tid = threadIdx.x;
    const int hw0 = blockIdx.x * 32;
    const int b = blockIdx.y, n = blockIdx.z;
    const int lane = tid & 31, w = tid >> 5;

#pragma unroll
    for (int pp = 0; pp < 4; pp++) {
        const int pt = w * 4 + pp;
        const int k = d_idxBuf[(b * NN + n) * HWHW + hw0 + pt];
        const float4 v = *((const float4*)(d_embedT + ((size_t)(n * KK + k)) * DD) + lane);
        const int d = lane * 4;
        qs[(d + 0) * 33 + pt] = v.x;
        qs[(d + 1) * 33 + pt] = v.y;
        qs[(d + 2) * 33 + pt] = v.z;
        qs[(d + 3) * 33 + pt] = v.w;
    }
    __syncthreads();

    float lsum = 0.f;
    const int hw = tid & 31, dh = tid >> 5;
#pragma unroll
    for (int d0 = 0; d0 < 128; d0 += 8) {
        const int d = d0 + dh;
        const size_t off = ((size_t)b * CC + n * DD + d) * HWHW + hw0 + hw;
        const float xv = __ldg(x + off);
        const float t = qs[d * 33 + hw] - xv;
        zq[off] = xv + t;
        lsum = fmaf(t, t, lsum);
    }
    red[tid] = lsum;
    __syncthreads();
    for (int s = 128; s; s >>= 1) { if (tid < s) red[tid] += red[tid + s]; __syncthreads(); }
    if (tid == 0) d_diffPartial[(blockIdx.z * 64 + blockIdx.y) * 32 + blockIdx.x] = red[0];
}

// ============================================================
// Kernel D: final diff + ppl
// ============================================================
__global__ void final_kernel(float* __restrict__ out_diff, float* __restrict__ out_ppl) {
    __shared__ float red[1024];
    __shared__ float ent[NN];
    const int tid = threadIdx.x;
    float s = 0.f;
#pragma unroll
    for (int r = 0; r < 8; r++) s += d_diffPartial[r * 1024 + tid];
    red[tid] = s;
    __syncthreads();
    for (int st = 512; st; st >>= 1) { if (tid < st) red[tid] += red[tid + st]; __syncthreads(); }
    if (tid == 0) *out_diff = red[0] / 33554432.0f;
    __syncthreads();
    for (int n = 0; n < NN; n++) {
        const float p = (float)d_counts[n * KK + tid] * (1.0f / 65536.0f);
        red[tid] = p * logf(p + 1e-10f);
        __syncthreads();
        for (int st = 512; st; st >>= 1) { if (tid < st) red[tid] += red[tid + st]; __syncthreads(); }
        if (tid == 0) ent[n] = red[0];
        __syncthreads();
    }
    if (tid == 0) {
        float ppl = 0.f;
        for (int n = 0; n < NN; n++) ppl += expf(-ent[n]);
        *out_ppl = ppl * 0.25f;
    }
}

// ============================================================
extern "C" void kernel_launch(void* const* d_in, const int* in_sizes, int n_in,
                              void* d_out, int out_size) {
    const float* x     = (const float*)d_in[0];
    const float* embed = (const float*)d_in[1];
    if (in_sizes[0] == NN * DD * KK) { x = (const float*)d_in[1]; embed = (const float*)d_in[0]; }

    float* out = (float*)d_out;
    float* zq   = out;
    float* diff = out + 33554432;
    float* argm = out + 33554433;
    float* ppl  = out + 33554433 + 262144;

    const int smem_bytes = SM_WORDS * (int)sizeof(float);   // 139,776
    cudaFuncSetAttribute(vq_mma, cudaFuncAttributeMaxDynamicSharedMemorySize, smem_bytes);

    prep_kernel<<<32, 128>>>(embed);
    vq_mma<<<dim3(512, 4), 256, smem_bytes>>>(x, embed, argm);
    epi_kernel<<<dim3(32, 64, 4), 256>>>(x, zq);
    final_kernel<<<1, 1024>>>(diff, ppl);
}